// round 11
// baseline (speedup 1.0000x reference)
#include <cuda_runtime.h>

// MiniTransformer B=131072, T=8, D=32, H=64, V=27, fp32.
// Warp-per-batch, lane j = feature dim.
//  - matmuls: packed fma.rn.f32x2 over t-pairs (transposed smem activations)
//  - weights stored TRANSPOSED + XOR-swizzled in smem: lane j's column is a
//    contiguous row, loaded 4-dims-at-a-time via conflict-free LDS.128
//    (cuts 256 scalar weight LDS/batch to 64 vector LDS)
//  - attention: smem row dots per (t,s-pair) lane + quad softmax
//  - layernorms: packed (sum,sumsq) f32x2 butterflies

namespace {
constexpr int T = 8;
constexpr int D = 32;
constexpr int H = 64;
constexpr int V = 27;
constexpr float EPS = 1e-5f;
constexpr int NWARP = 4;
constexpr int STR = 12;        // transposed activation tile row stride
constexpr int QS  = 36;        // Q/K score-row stride (bank-conflict-free)
constexpr int KB  = 288;       // K rows base (floats)
constexpr int AB  = 576;       // attn tile base (floats), stride 12
constexpr int GRID = 1480;
}

__device__ __forceinline__ unsigned long long pack2(float a) {
    unsigned long long r;
    asm("mov.b64 %0, {%1, %1};" : "=l"(r) : "f"(a));
    return r;
}
__device__ __forceinline__ unsigned long long pack2f(float a, float b) {
    unsigned long long r;
    asm("mov.b64 %0, {%1, %2};" : "=l"(r) : "f"(a), "f"(b));
    return r;
}
__device__ __forceinline__ void unpack2(unsigned long long p, float& a, float& b) {
    asm("mov.b64 {%0, %1}, %2;" : "=f"(a), "=f"(b) : "l"(p));
}
__device__ __forceinline__ unsigned long long add2(unsigned long long a,
                                                   unsigned long long b) {
    unsigned long long r;
    asm("add.rn.f32x2 %0, %1, %2;" : "=l"(r) : "l"(a), "l"(b));
    return r;
}
__device__ __forceinline__ void ffma2(unsigned long long& d,
                                      unsigned long long a,
                                      unsigned long long b) {
    asm("fma.rn.f32x2 %0, %1, %2, %0;" : "+l"(d) : "l"(a), "l"(b));
}
__device__ __forceinline__ unsigned long long warp_sum2(unsigned long long p) {
    #pragma unroll
    for (int off = 16; off > 0; off >>= 1) {
        unsigned long long o = __shfl_xor_sync(0xffffffffu, p, off);
        p = add2(p, o);
    }
    return p;
}

union Pack8 {                  // 8 floats = 4 f32x2 pairs (t0..t7)
    unsigned long long u[4];
    float f[8];
    float4 v4[2];
};
union Pack4 {                  // 4 floats = 2 f32x2 pairs
    unsigned long long u[2];
    float f[4];
    float4 v4;
};

__global__ __launch_bounds__(NWARP * 32, 4) void mt_kernel(
    const int*   __restrict__ tokens,
    const float* __restrict__ tok_emb,
    const float* __restrict__ pos_emb,
    const float* __restrict__ gWq,
    const float* __restrict__ gWk,
    const float* __restrict__ gWv,
    const float* __restrict__ gW1,
    const float* __restrict__ gW2,
    const float* __restrict__ gWo,
    float* __restrict__ out,
    int nB, int nwarps_total)
{
    __shared__ float sTE[V * D];
    __shared__ float sPos[T * D];
    // transposed + swizzled weight tiles: wT[j][d], 16B chunk c -> c ^ (j&7)
    __shared__ __align__(16) float sWqT[D * D];
    __shared__ __align__(16) float sWkT[D * D];
    __shared__ __align__(16) float sWvT[D * D];
    __shared__ __align__(16) float sW1aT[D * D];   // W1 cols 0..31
    __shared__ __align__(16) float sW1bT[D * D];   // W1 cols 32..63
    __shared__ __align__(16) float sW2T[D * H];    // [j][h], stride 64
    __shared__ __align__(16) float sWoT[D * D];    // Wout cols padded
    __shared__ __align__(16) float scrT_all[NWARP][H * STR];  // 768 f/warp

    const int tid = threadIdx.x;
    const int nthr = NWARP * 32;

    for (int i = tid; i < V * D; i += nthr) sTE[i] = tok_emb[i];
    for (int i = tid; i < T * D; i += nthr) sPos[i] = pos_emb[i];
    for (int i = tid; i < D * D; i += nthr) {
        const int jj = i >> 5, d = i & 31;
        const int phys = jj * 32 + ((((d >> 2) ^ (jj & 7)) << 2) | (d & 3));
        sWqT[phys]  = gWq[d * D + jj];
        sWkT[phys]  = gWk[d * D + jj];
        sWvT[phys]  = gWv[d * D + jj];
        sW1aT[phys] = gW1[d * H + jj];
        sW1bT[phys] = gW1[d * H + jj + 32];
        sWoT[phys]  = (jj < V) ? gWo[d * V + jj] : 0.0f;
    }
    for (int i = tid; i < D * H; i += nthr) {
        const int jj = i >> 6, h = i & 63;
        const int phys = jj * 64 + ((((h >> 2) ^ (jj & 7)) << 2) | (h & 3));
        sW2T[phys] = gW2[h * D + jj];
    }
    __syncthreads();

    const int j = tid & 31;
    float* scrT = scrT_all[tid >> 5];
    const int warp_global = blockIdx.x * NWARP + (tid >> 5);

    const int tq = j >> 2;      // attention: this lane's query row
    const int p  = j & 3;       // attention: this lane's s-pair index
    const int jsw = j & 7;      // weight swizzle key

    for (int b = warp_global; b < nB; b += nwarps_total) {
        // ---- embeddings ----
        int mytok = 0;
        if (j < T) mytok = tokens[b * T + j];

        Pack8 X;
        #pragma unroll
        for (int t = 0; t < T; ++t) {
            int tok = __shfl_sync(0xffffffffu, mytok, t);
            X.f[t] = sTE[tok * D + j] + sPos[t * D + j];
        }
        __syncwarp();
        *(float4*)&scrT[j * STR]     = X.v4[0];
        *(float4*)&scrT[j * STR + 4] = X.v4[1];
        __syncwarp();

        // ---- Q,K,V = x @ {Wq,Wk,Wv}, vector weight loads ----
        Pack8 Q, K, Vv;
        #pragma unroll
        for (int i = 0; i < 4; ++i) { Q.u[i] = 0ull; K.u[i] = 0ull; Vv.u[i] = 0ull; }

        #pragma unroll
        for (int dc = 0; dc < 8; ++dc) {
            const int sw4 = ((dc ^ jsw) << 2);
            Pack4 wq4, wk4, wv4;
            wq4.v4 = *(const float4*)&sWqT[j * 32 + sw4];
            wk4.v4 = *(const float4*)&sWkT[j * 32 + sw4];
            wv4.v4 = *(const float4*)&sWvT[j * 32 + sw4];
            #pragma unroll
            for (int i = 0; i < 4; ++i) {
                const int d = dc * 4 + i;
                Pack8 xp;
                xp.v4[0] = *(const float4*)&scrT[d * STR];
                xp.v4[1] = *(const float4*)&scrT[d * STR + 4];
                const unsigned long long wq = pack2(wq4.f[i]);
                const unsigned long long wk = pack2(wk4.f[i]);
                const unsigned long long wv = pack2(wv4.f[i]);
                #pragma unroll
                for (int u = 0; u < 4; ++u) {
                    ffma2(Q.u[u],  xp.u[u], wq);
                    ffma2(K.u[u],  xp.u[u], wk);
                    ffma2(Vv.u[u], xp.u[u], wv);
                }
            }
        }
        __syncwarp();   // x tile reads done before Q/K rows overwrite it

        // ---- scatter Q,K as rows ----
        #pragma unroll
        for (int t = 0; t < T; ++t) {
            scrT[t * QS + j]      = Q.f[t];
            scrT[KB + t * QS + j] = K.f[t];
        }
        __syncwarp();

        // ---- scores: lane (tq,p) dots Q[tq]·K[2p], Q[tq]·K[2p+1] ----
        unsigned long long acc0 = 0ull, acc1 = 0ull;
        #pragma unroll
        for (int c = 0; c < 8; ++c) {
            Pack4 qv, k0, k1;
            qv.v4 = *(const float4*)&scrT[tq * QS + c * 4];
            k0.v4 = *(const float4*)&scrT[KB + (2 * p) * QS + c * 4];
            k1.v4 = *(const float4*)&scrT[KB + (2 * p + 1) * QS + c * 4];
            ffma2(acc0, qv.u[0], k0.u[0]);
            ffma2(acc0, qv.u[1], k0.u[1]);
            ffma2(acc1, qv.u[0], k1.u[0]);
            ffma2(acc1, qv.u[1], k1.u[1]);
        }
        float a0x, a0y, a1x, a1y;
        unpack2(acc0, a0x, a0y);
        unpack2(acc1, a1x, a1y);
        float slo = a0x + a0y;
        float shi = a1x + a1y;
        if (2 * p     > tq) slo = -1e30f;
        if (2 * p + 1 > tq) shi = -1e30f;

        // ---- softmax within the 4-lane quad owning row tq ----
        float m = fmaxf(slo, shi);
        m = fmaxf(m, __shfl_xor_sync(0xffffffffu, m, 1));
        m = fmaxf(m, __shfl_xor_sync(0xffffffffu, m, 2));
        float elo = __expf(slo - m);
        float ehi = __expf(shi - m);
        float den = elo + ehi;
        den += __shfl_xor_sync(0xffffffffu, den, 1);
        den += __shfl_xor_sync(0xffffffffu, den, 2);
        float inv = 1.0f / den;
        scrT[AB + (2 * p) * STR + tq]     = elo * inv;
        scrT[AB + (2 * p + 1) * STR + tq] = ehi * inv;
        __syncwarp();

        // ---- out = attn @ V ----
        Pack8 O;
        #pragma unroll
        for (int i = 0; i < 4; ++i) O.u[i] = 0ull;
        #pragma unroll
        for (int s = 0; s < T; ++s) {
            Pack8 A_;
            A_.v4[0] = *(const float4*)&scrT[AB + s * STR];
            A_.v4[1] = *(const float4*)&scrT[AB + s * STR + 4];
            const unsigned long long wv = pack2(Vv.f[s]);
            #pragma unroll
            for (int i = 0; i < 4; ++i)
                ffma2(O.u[i], A_.u[i], wv);
        }

        // ---- residual + LayerNorm 1 ----
        Pack8 L;
        #pragma unroll
        for (int t = 0; t < T; ++t) {
            float h = O.f[t] + X.f[t];
            float s1, s2;
            unpack2(warp_sum2(pack2f(h, h * h)), s1, s2);
            float mu  = s1 * (1.0f / D);
            float var = s2 * (1.0f / D) - mu * mu;
            L.f[t] = (h - mu) * rsqrtf(var + EPS);
        }
        __syncwarp();
        *(float4*)&scrT[j * STR]     = L.v4[0];
        *(float4*)&scrT[j * STR + 4] = L.v4[1];
        __syncwarp();

        // ---- MLP up: y1 = relu(ln1 @ W1) ----
        Pack8 Ya, Yb;
        #pragma unroll
        for (int i = 0; i < 4; ++i) { Ya.u[i] = 0ull; Yb.u[i] = 0ull; }

        #pragma unroll
        for (int dc = 0; dc < 8; ++dc) {
            const int sw4 = ((dc ^ jsw) << 2);
            Pack4 wa4, wb4;
            wa4.v4 = *(const float4*)&sW1aT[j * 32 + sw4];
            wb4.v4 = *(const float4*)&sW1bT[j * 32 + sw4];
            #pragma unroll
            for (int i = 0; i < 4; ++i) {
                const int d = dc * 4 + i;
                Pack8 xp;
                xp.v4[0] = *(const float4*)&scrT[d * STR];
                xp.v4[1] = *(const float4*)&scrT[d * STR + 4];
                const unsigned long long wa = pack2(wa4.f[i]);
                const unsigned long long wb = pack2(wb4.f[i]);
                #pragma unroll
                for (int u = 0; u < 4; ++u) {
                    ffma2(Ya.u[u], xp.u[u], wa);
                    ffma2(Yb.u[u], xp.u[u], wb);
                }
            }
        }
        #pragma unroll
        for (int i = 0; i < 8; ++i) {
            Ya.f[i] = fmaxf(Ya.f[i], 0.0f);
            Yb.f[i] = fmaxf(Yb.f[i], 0.0f);
        }
        __syncwarp();
        *(float4*)&scrT[j * STR]            = Ya.v4[0];
        *(float4*)&scrT[j * STR + 4]        = Ya.v4[1];
        *(float4*)&scrT[(j + 32) * STR]     = Yb.v4[0];
        *(float4*)&scrT[(j + 32) * STR + 4] = Yb.v4[1];
        __syncwarp();

        // ---- MLP down: y2 = y1 @ W2 ----
        Pack8 Y2;
        #pragma unroll
        for (int i = 0; i < 4; ++i) Y2.u[i] = 0ull;

        #pragma unroll
        for (int hc = 0; hc < 16; ++hc) {
            const int sw4 = (((hc ^ jsw) & 15) << 2) | ((hc & 8) << 2);
            // swizzle only low 3 bits of chunk index; bit 3 passes through
            const int chunk = ((hc & 8) | ((hc ^ jsw) & 7)) << 2;
            Pack4 w4;
            w4.v4 = *(const float4*)&sW2T[j * 64 + chunk];
            (void)sw4;
            #pragma unroll
            for (int i = 0; i < 4; ++i) {
                const int h = hc * 4 + i;
                Pack8 xp;
                xp.v4[0] = *(const float4*)&scrT[h * STR];
                xp.v4[1] = *(const float4*)&scrT[h * STR + 4];
                const unsigned long long w = pack2(w4.f[i]);
                #pragma unroll
                for (int u = 0; u < 4; ++u)
                    ffma2(Y2.u[u], xp.u[u], w);
            }
        }

        // ---- residual + LayerNorm 2 ----
        Pack8 Z;
        #pragma unroll
        for (int t = 0; t < T; ++t) {
            float h = Y2.f[t] + L.f[t];
            float s1, s2;
            unpack2(warp_sum2(pack2f(h, h * h)), s1, s2);
            float mu  = s1 * (1.0f / D);
            float var = s2 * (1.0f / D) - mu * mu;
            Z.f[t] = (h - mu) * rsqrtf(var + EPS);
        }
        __syncwarp();
        *(float4*)&scrT[j * STR]     = Z.v4[0];
        *(float4*)&scrT[j * STR + 4] = Z.v4[1];
        __syncwarp();

        // ---- logits = z @ Wout ----
        Pack8 Lg;
        #pragma unroll
        for (int i = 0; i < 4; ++i) Lg.u[i] = 0ull;

        #pragma unroll
        for (int dc = 0; dc < 8; ++dc) {
            const int sw4 = ((dc ^ jsw) << 2);
            Pack4 w4;
            w4.v4 = *(const float4*)&sWoT[j * 32 + sw4];
            #pragma unroll
            for (int i = 0; i < 4; ++i) {
                const int d = dc * 4 + i;
                Pack8 xp;
                xp.v4[0] = *(const float4*)&scrT[d * STR];
                xp.v4[1] = *(const float4*)&scrT[d * STR + 4];
                const unsigned long long w = pack2(w4.f[i]);
                #pragma unroll
                for (int u = 0; u < 4; ++u)
                    ffma2(Lg.u[u], xp.u[u], w);
            }
        }
        __syncwarp();   // scrT reused next iteration

        if (j < V) {
            const size_t base = (size_t)b * (T * V);
            #pragma unroll
            for (int t = 0; t < T; ++t)
                out[base + t * V + j] = Lg.f[t];
        }
    }
}

extern "C" void kernel_launch(void* const* d_in, const int* in_sizes, int n_in,
                              void* d_out, int out_size)
{
    const int*   tokens  = (const int*)  d_in[0];
    const float* tok_emb = (const float*)d_in[1];
    const float* pos_emb = (const float*)d_in[2];
    const float* Wq      = (const float*)d_in[3];
    const float* Wk      = (const float*)d_in[4];
    const float* Wv      = (const float*)d_in[5];
    const float* W1      = (const float*)d_in[6];
    const float* W2      = (const float*)d_in[7];
    const float* Wout    = (const float*)d_in[8];
    float* out = (float*)d_out;

    const int nB = in_sizes[0] / T;
    const int nwarps_total = GRID * NWARP;

    mt_kernel<<<GRID, NWARP * 32>>>(tokens, tok_emb, pos_emb,
                                    Wq, Wk, Wv, W1, W2, Wout,
                                    out, nB, nwarps_total);
}

// round 12
// speedup vs baseline: 1.0429x; 1.0429x over previous
#include <cuda_runtime.h>

// MiniTransformer B=131072, T=8, D=32, H=64, V=27, fp32.
// Warp-per-TWO-batches, lane j = feature dim. R11 design:
//  - revert R9 weight swizzle (weight LDS.32 rows are already 1 wavefront;
//    vectorizing them saved issue slots, not L1 data-path — and L1 is the wall)
//  - each warp processes 2 batches: every weight LDS is shared by both,
//    cutting weight wavefronts per batch in half (~-19% total wavefronts)
//  - matmuls: packed fma.rn.f32x2 over t-pairs
//  - attention: smem row dots per (t,s-pair) lane + quad softmax
//  - layernorms: packed (sum,sumsq) f32x2 butterflies

namespace {
constexpr int T = 8;
constexpr int D = 32;
constexpr int H = 64;
constexpr int V = 27;
constexpr float EPS = 1e-5f;
constexpr int NWARP = 4;
constexpr int STR = 12;        // transposed activation tile row stride
constexpr int QS  = 36;        // Q/K score-row stride
constexpr int KB  = 288;       // K rows base (floats, within slot)
constexpr int AB  = 576;       // attn tile base (floats, within slot)
constexpr int SLOT = 768;      // floats per batch slot
constexpr int GRID = 1480;

// dynamic shared layout (float offsets)
constexpr int OFF_TE  = 0;                 // 864
constexpr int OFF_POS = OFF_TE + V * D;    // 1120
constexpr int OFF_WQ  = OFF_POS + T * D;   // 1376 -> wait computed at compile
constexpr int OFF_WK  = OFF_WQ + D * D;
constexpr int OFF_WV  = OFF_WK + D * D;
constexpr int OFF_W1  = OFF_WV + D * D;
constexpr int OFF_W2  = OFF_W1 + D * H;
constexpr int OFF_WO  = OFF_W2 + H * D;
constexpr int OFF_SCR = OFF_WO + D * D;
constexpr int SMEM_FLOATS = OFF_SCR + NWARP * 2 * SLOT;
constexpr int SMEM_BYTES  = SMEM_FLOATS * 4;   // 61824 B
}

__device__ __forceinline__ unsigned long long pack2(float a) {
    unsigned long long r;
    asm("mov.b64 %0, {%1, %1};" : "=l"(r) : "f"(a));
    return r;
}
__device__ __forceinline__ unsigned long long pack2f(float a, float b) {
    unsigned long long r;
    asm("mov.b64 %0, {%1, %2};" : "=l"(r) : "f"(a), "f"(b));
    return r;
}
__device__ __forceinline__ void unpack2(unsigned long long p, float& a, float& b) {
    asm("mov.b64 {%0, %1}, %2;" : "=f"(a), "=f"(b) : "l"(p));
}
__device__ __forceinline__ unsigned long long add2(unsigned long long a,
                                                   unsigned long long b) {
    unsigned long long r;
    asm("add.rn.f32x2 %0, %1, %2;" : "=l"(r) : "l"(a), "l"(b));
    return r;
}
__device__ __forceinline__ void ffma2(unsigned long long& d,
                                      unsigned long long a,
                                      unsigned long long b) {
    asm("fma.rn.f32x2 %0, %1, %2, %0;" : "+l"(d) : "l"(a), "l"(b));
}
__device__ __forceinline__ unsigned long long warp_sum2(unsigned long long p) {
    #pragma unroll
    for (int off = 16; off > 0; off >>= 1) {
        unsigned long long o = __shfl_xor_sync(0xffffffffu, p, off);
        p = add2(p, o);
    }
    return p;
}

union Pack8 {                  // 8 floats = 4 f32x2 pairs (t0..t7)
    unsigned long long u[4];
    float f[8];
    float4 v4[2];
};
union Pack4 {                  // 4 floats = 2 f32x2 pairs
    unsigned long long u[2];
    float f[4];
    float4 v4;
};

__global__ __launch_bounds__(NWARP * 32, 3) void mt_kernel(
    const int*   __restrict__ tokens,
    const float* __restrict__ tok_emb,
    const float* __restrict__ pos_emb,
    const float* __restrict__ gWq,
    const float* __restrict__ gWk,
    const float* __restrict__ gWv,
    const float* __restrict__ gW1,
    const float* __restrict__ gW2,
    const float* __restrict__ gWo,
    float* __restrict__ out,
    int nB, int nwarps_total)
{
    extern __shared__ __align__(16) float smem[];
    float* sTE  = smem + OFF_TE;
    float* sPos = smem + OFF_POS;
    float* sWq  = smem + OFF_WQ;
    float* sWk  = smem + OFF_WK;
    float* sWv  = smem + OFF_WV;
    float* sW1  = smem + OFF_W1;
    float* sW2  = smem + OFF_W2;
    float* sWo  = smem + OFF_WO;

    const int tid = threadIdx.x;
    const int nthr = NWARP * 32;

    for (int i = tid; i < V * D; i += nthr) sTE[i] = tok_emb[i];
    for (int i = tid; i < T * D; i += nthr) sPos[i] = pos_emb[i];
    for (int i = tid; i < D * D; i += nthr) {
        sWq[i] = gWq[i];
        sWk[i] = gWk[i];
        sWv[i] = gWv[i];
    }
    for (int i = tid; i < D * H; i += nthr) sW1[i] = gW1[i];
    for (int i = tid; i < H * D; i += nthr) sW2[i] = gW2[i];
    for (int i = tid; i < D * 32; i += nthr) {
        int d = i >> 5, jv = i & 31;
        sWo[i] = (jv < V) ? gWo[d * V + jv] : 0.0f;
    }
    __syncthreads();

    const int j = tid & 31;
    const int wip = tid >> 5;
    float* const scr0 = smem + OFF_SCR + wip * 2 * SLOT;
    float* const scr1 = scr0 + SLOT;
    const int warp_global = blockIdx.x * NWARP + wip;

    const int tq = j >> 2;      // attention: this lane's query row
    const int p  = j & 3;       // attention: this lane's s-pair index

    // nB is even: pairs (2*ib, 2*ib+1), no tail handling needed
    for (int ib = warp_global; 2 * ib + 1 < nB; ib += nwarps_total) {
        const int b0 = 2 * ib;
        const int b1 = b0 + 1;

        // ---- embeddings for both slots ----
        int myt0 = 0, myt1 = 0;
        if (j < T) {
            myt0 = tokens[b0 * T + j];
            myt1 = tokens[b1 * T + j];
        }

        Pack8 X0, X1;
        #pragma unroll
        for (int t = 0; t < T; ++t) {
            const int t0 = __shfl_sync(0xffffffffu, myt0, t);
            const int t1 = __shfl_sync(0xffffffffu, myt1, t);
            const float pe = sPos[t * D + j];
            X0.f[t] = sTE[t0 * D + j] + pe;
            X1.f[t] = sTE[t1 * D + j] + pe;
        }
        __syncwarp();
        *(float4*)&scr0[j * STR]     = X0.v4[0];
        *(float4*)&scr0[j * STR + 4] = X0.v4[1];
        *(float4*)&scr1[j * STR]     = X1.v4[0];
        *(float4*)&scr1[j * STR + 4] = X1.v4[1];
        __syncwarp();

        // ---- Q,K,V for both slots; each weight LDS serves both ----
        Pack8 Q0, K0, V0, Q1, K1, V1;
        #pragma unroll
        for (int i = 0; i < 4; ++i) {
            Q0.u[i] = 0ull; K0.u[i] = 0ull; V0.u[i] = 0ull;
            Q1.u[i] = 0ull; K1.u[i] = 0ull; V1.u[i] = 0ull;
        }

        #pragma unroll
        for (int d = 0; d < D; ++d) {
            const unsigned long long wq = pack2(sWq[d * D + j]);
            const unsigned long long wk = pack2(sWk[d * D + j]);
            const unsigned long long wv = pack2(sWv[d * D + j]);
            Pack8 xa, xb;
            xa.v4[0] = *(const float4*)&scr0[d * STR];
            xa.v4[1] = *(const float4*)&scr0[d * STR + 4];
            xb.v4[0] = *(const float4*)&scr1[d * STR];
            xb.v4[1] = *(const float4*)&scr1[d * STR + 4];
            #pragma unroll
            for (int i = 0; i < 4; ++i) {
                ffma2(Q0.u[i], xa.u[i], wq);
                ffma2(K0.u[i], xa.u[i], wk);
                ffma2(V0.u[i], xa.u[i], wv);
                ffma2(Q1.u[i], xb.u[i], wq);
                ffma2(K1.u[i], xb.u[i], wk);
                ffma2(V1.u[i], xb.u[i], wv);
            }
        }
        __syncwarp();

        // ---- attention per slot (independent scratch regions) ----
        Pack8 O0, O1;
        #pragma unroll
        for (int sl = 0; sl < 2; ++sl) {
            float* const scr = sl ? scr1 : scr0;
            const Pack8& Q = sl ? Q1 : Q0;
            const Pack8& K = sl ? K1 : K0;
            const Pack8& Vv = sl ? V1 : V0;
            Pack8& O = sl ? O1 : O0;

            // scatter Q,K rows
            #pragma unroll
            for (int t = 0; t < T; ++t) {
                scr[t * QS + j]      = Q.f[t];
                scr[KB + t * QS + j] = K.f[t];
            }
            __syncwarp();

            // scores: lane (tq,p) dots Q[tq]·K[2p], Q[tq]·K[2p+1]
            unsigned long long acc0 = 0ull, acc1 = 0ull;
            #pragma unroll
            for (int c = 0; c < 8; ++c) {
                Pack4 qv, k0, k1;
                qv.v4 = *(const float4*)&scr[tq * QS + c * 4];
                k0.v4 = *(const float4*)&scr[KB + (2 * p) * QS + c * 4];
                k1.v4 = *(const float4*)&scr[KB + (2 * p + 1) * QS + c * 4];
                ffma2(acc0, qv.u[0], k0.u[0]);
                ffma2(acc0, qv.u[1], k0.u[1]);
                ffma2(acc1, qv.u[0], k1.u[0]);
                ffma2(acc1, qv.u[1], k1.u[1]);
            }
            float a0x, a0y, a1x, a1y;
            unpack2(acc0, a0x, a0y);
            unpack2(acc1, a1x, a1y);
            float slo = a0x + a0y;
            float shi = a1x + a1y;
            if (2 * p     > tq) slo = -1e30f;
            if (2 * p + 1 > tq) shi = -1e30f;

            // softmax within the 4-lane quad owning row tq
            float m = fmaxf(slo, shi);
            m = fmaxf(m, __shfl_xor_sync(0xffffffffu, m, 1));
            m = fmaxf(m, __shfl_xor_sync(0xffffffffu, m, 2));
            float elo = __expf(slo - m);
            float ehi = __expf(shi - m);
            float den = elo + ehi;
            den += __shfl_xor_sync(0xffffffffu, den, 1);
            den += __shfl_xor_sync(0xffffffffu, den, 2);
            float inv = 1.0f / den;
            scr[AB + (2 * p) * STR + tq]     = elo * inv;
            scr[AB + (2 * p + 1) * STR + tq] = ehi * inv;
            __syncwarp();

            // out = attn @ V
            #pragma unroll
            for (int i = 0; i < 4; ++i) O.u[i] = 0ull;
            #pragma unroll
            for (int s = 0; s < T; ++s) {
                Pack8 A_;
                A_.v4[0] = *(const float4*)&scr[AB + s * STR];
                A_.v4[1] = *(const float4*)&scr[AB + s * STR + 4];
                const unsigned long long wv = pack2(Vv.f[s]);
                #pragma unroll
                for (int i = 0; i < 4; ++i)
                    ffma2(O.u[i], A_.u[i], wv);
            }
        }

        // ---- residual + LayerNorm 1, both slots ----
        Pack8 L0, L1;
        #pragma unroll
        for (int t = 0; t < T; ++t) {
            float h0 = O0.f[t] + X0.f[t];
            float h1 = O1.f[t] + X1.f[t];
            float s1, s2;
            unpack2(warp_sum2(pack2f(h0, h0 * h0)), s1, s2);
            float mu = s1 * (1.0f / D);
            float var = s2 * (1.0f / D) - mu * mu;
            L0.f[t] = (h0 - mu) * rsqrtf(var + EPS);
            unpack2(warp_sum2(pack2f(h1, h1 * h1)), s1, s2);
            mu = s1 * (1.0f / D);
            var = s2 * (1.0f / D) - mu * mu;
            L1.f[t] = (h1 - mu) * rsqrtf(var + EPS);
        }
        __syncwarp();
        *(float4*)&scr0[j * STR]     = L0.v4[0];
        *(float4*)&scr0[j * STR + 4] = L0.v4[1];
        *(float4*)&scr1[j * STR]     = L1.v4[0];
        *(float4*)&scr1[j * STR + 4] = L1.v4[1];
        __syncwarp();

        // ---- MLP up: y1 = relu(ln1 @ W1), shared weight loads ----
        Pack8 Ya0, Yb0, Ya1, Yb1;
        #pragma unroll
        for (int i = 0; i < 4; ++i) {
            Ya0.u[i] = 0ull; Yb0.u[i] = 0ull;
            Ya1.u[i] = 0ull; Yb1.u[i] = 0ull;
        }

        #pragma unroll
        for (int d = 0; d < D; ++d) {
            const unsigned long long wa = pack2(sW1[d * H + j]);
            const unsigned long long wb = pack2(sW1[d * H + j + 32]);
            Pack8 xa, xb;
            xa.v4[0] = *(const float4*)&scr0[d * STR];
            xa.v4[1] = *(const float4*)&scr0[d * STR + 4];
            xb.v4[0] = *(const float4*)&scr1[d * STR];
            xb.v4[1] = *(const float4*)&scr1[d * STR + 4];
            #pragma unroll
            for (int i = 0; i < 4; ++i) {
                ffma2(Ya0.u[i], xa.u[i], wa);
                ffma2(Yb0.u[i], xa.u[i], wb);
                ffma2(Ya1.u[i], xb.u[i], wa);
                ffma2(Yb1.u[i], xb.u[i], wb);
            }
        }
        #pragma unroll
        for (int i = 0; i < 8; ++i) {
            Ya0.f[i] = fmaxf(Ya0.f[i], 0.0f);
            Yb0.f[i] = fmaxf(Yb0.f[i], 0.0f);
            Ya1.f[i] = fmaxf(Ya1.f[i], 0.0f);
            Yb1.f[i] = fmaxf(Yb1.f[i], 0.0f);
        }
        __syncwarp();
        *(float4*)&scr0[j * STR]            = Ya0.v4[0];
        *(float4*)&scr0[j * STR + 4]        = Ya0.v4[1];
        *(float4*)&scr0[(j + 32) * STR]     = Yb0.v4[0];
        *(float4*)&scr0[(j + 32) * STR + 4] = Yb0.v4[1];
        *(float4*)&scr1[j * STR]            = Ya1.v4[0];
        *(float4*)&scr1[j * STR + 4]        = Ya1.v4[1];
        *(float4*)&scr1[(j + 32) * STR]     = Yb1.v4[0];
        *(float4*)&scr1[(j + 32) * STR + 4] = Yb1.v4[1];
        __syncwarp();

        // ---- MLP down: y2 = y1 @ W2, shared weight loads ----
        Pack8 Y20, Y21;
        #pragma unroll
        for (int i = 0; i < 4; ++i) { Y20.u[i] = 0ull; Y21.u[i] = 0ull; }

        #pragma unroll
        for (int h = 0; h < H; ++h) {
            const unsigned long long w = pack2(sW2[h * D + j]);
            Pack8 xa, xb;
            xa.v4[0] = *(const float4*)&scr0[h * STR];
            xa.v4[1] = *(const float4*)&scr0[h * STR + 4];
            xb.v4[0] = *(const float4*)&scr1[h * STR];
            xb.v4[1] = *(const float4*)&scr1[h * STR + 4];
            #pragma unroll
            for (int i = 0; i < 4; ++i) {
                ffma2(Y20.u[i], xa.u[i], w);
                ffma2(Y21.u[i], xb.u[i], w);
            }
        }

        // ---- residual + LayerNorm 2, both slots ----
        Pack8 Z0, Z1;
        #pragma unroll
        for (int t = 0; t < T; ++t) {
            float h0 = Y20.f[t] + L0.f[t];
            float h1 = Y21.f[t] + L1.f[t];
            float s1, s2;
            unpack2(warp_sum2(pack2f(h0, h0 * h0)), s1, s2);
            float mu = s1 * (1.0f / D);
            float var = s2 * (1.0f / D) - mu * mu;
            Z0.f[t] = (h0 - mu) * rsqrtf(var + EPS);
            unpack2(warp_sum2(pack2f(h1, h1 * h1)), s1, s2);
            mu = s1 * (1.0f / D);
            var = s2 * (1.0f / D) - mu * mu;
            Z1.f[t] = (h1 - mu) * rsqrtf(var + EPS);
        }
        __syncwarp();
        *(float4*)&scr0[j * STR]     = Z0.v4[0];
        *(float4*)&scr0[j * STR + 4] = Z0.v4[1];
        *(float4*)&scr1[j * STR]     = Z1.v4[0];
        *(float4*)&scr1[j * STR + 4] = Z1.v4[1];
        __syncwarp();

        // ---- logits = z @ Wout, shared weight loads ----
        Pack8 Lg0, Lg1;
        #pragma unroll
        for (int i = 0; i < 4; ++i) { Lg0.u[i] = 0ull; Lg1.u[i] = 0ull; }

        #pragma unroll
        for (int d = 0; d < D; ++d) {
            const unsigned long long w = pack2(sWo[d * 32 + j]);
            Pack8 xa, xb;
            xa.v4[0] = *(const float4*)&scr0[d * STR];
            xa.v4[1] = *(const float4*)&scr0[d * STR + 4];
            xb.v4[0] = *(const float4*)&scr1[d * STR];
            xb.v4[1] = *(const float4*)&scr1[d * STR + 4];
            #pragma unroll
            for (int i = 0; i < 4; ++i) {
                ffma2(Lg0.u[i], xa.u[i], w);
                ffma2(Lg1.u[i], xb.u[i], w);
            }
        }
        __syncwarp();   // scratch reused next iteration

        if (j < V) {
            const size_t base0 = (size_t)b0 * (T * V);
            const size_t base1 = (size_t)b1 * (T * V);
            #pragma unroll
            for (int t = 0; t < T; ++t) {
                out[base0 + t * V + j] = Lg0.f[t];
                out[base1 + t * V + j] = Lg1.f[t];
            }
        }
    }
}

extern "C" void kernel_launch(void* const* d_in, const int* in_sizes, int n_in,
                              void* d_out, int out_size)
{
    const int*   tokens  = (const int*)  d_in[0];
    const float* tok_emb = (const float*)d_in[1];
    const float* pos_emb = (const float*)d_in[2];
    const float* Wq      = (const float*)d_in[3];
    const float* Wk      = (const float*)d_in[4];
    const float* Wv      = (const float*)d_in[5];
    const float* W1      = (const float*)d_in[6];
    const float* W2      = (const float*)d_in[7];
    const float* Wout    = (const float*)d_in[8];
    float* out = (float*)d_out;

    const int nB = in_sizes[0] / T;
    const int nwarps_total = GRID * NWARP;

    cudaFuncSetAttribute(mt_kernel,
                         cudaFuncAttributeMaxDynamicSharedMemorySize,
                         SMEM_BYTES);

    mt_kernel<<<GRID, NWARP * 32, SMEM_BYTES>>>(tokens, tok_emb, pos_emb,
                                                Wq, Wk, Wv, W1, W2, Wout,
                                                out, nB, nwarps_total);
}